// round 1
// baseline (speedup 1.0000x reference)
#include <cuda_runtime.h>
#include <math.h>

// ---------------------------------------------------------------------------
// Problem structure (LMAX=4, taus=16, t_O=16):
//   42 CG triples, T_FF = {1280,2048,2560,2560,2304} channels per degree,
//   B=256, input/output rows = 400 (complex), W = 172032 complex.
// Pipeline:
//   k_init   : zero sumsq, build CG coefficient table (double precision)
//   k_cg     : fragment tensor product -> g_Xr/g_Xi [c][m*256+b], sumsq atomics
//   k_prepw  : fold BN scale 1/(sqrt(var)+eps) into weights -> g_W2[c][o][ri]
//   k_gemm   : complex GEMM (16 K-slices) -> g_partial (deterministic)
//   k_reduce : sum K-slices, scatter into the harness output layout
// ---------------------------------------------------------------------------

#define NT 42

__constant__ int c_tL[NT]  = {0,0,0,0,0, 1,1,1,1,1,1,1,1, 2,2,2,2,2,2,2,2,2,2,
                              3,3,3,3,3,3,3,3,3,3, 4,4,4,4,4,4,4,4,4};
__constant__ int c_tL1[NT] = {0,1,2,3,4, 1,1,2,2,3,3,4,4, 1,2,2,2,3,3,3,4,4,4,
                              2,2,3,3,3,3,4,4,4,4, 2,3,3,3,4,4,4,4,4};
__constant__ int c_tL2[NT] = {0,1,2,3,4, 0,1,1,2,2,3,3,4, 1,0,1,2,1,2,3,2,3,4,
                              1,2,0,1,2,3,1,2,3,4, 2,1,2,3,0,1,2,3,4};
__constant__ int c_tRank[NT]={0,1,2,3,4, 0,1,2,3,4,5,6,7, 0,1,2,3,4,5,6,7,8,9,
                              0,1,2,3,4,5,6,7,8,9, 0,1,2,3,4,5,6,7,8};

__constant__ int c_chanbase[6]   = {0,1280,3328,5888,8448,10752};
__constant__ int c_xbase[5]      = {0,327680,1900544,5177344,9764864};
__constant__ int c_N[5]          = {256,768,1280,1792,2304};
__constant__ int c_inoff[5]      = {0,16,64,144,256};
__constant__ int c_TFF[5]        = {1280,2048,2560,2560,2304};
__constant__ int c_woff[5]       = {0,20480,53248,94208,135168};
__constant__ int c_pobase[6]     = {0,8192,32768,73728,131072,204800};
__constant__ int c_gemmPrefix[6] = {0,32,128,288,512,800};

// scratch (static __device__ globals: the sanctioned no-alloc scratch path)
__device__ float g_cg[NT * 81];
__device__ float g_sumsq[10752];
__device__ float g_Xr[15073280];
__device__ float g_Xi[15073280];
__device__ float g_W2[344064];          // [chan][o][ri]
__device__ float g_partial[3276800];    // 16 K-slices x 204800

// -------------------------- CG coefficients --------------------------------
__device__ double dfact(int n) {
    double r = 1.0;
    for (int i = 2; i <= n; ++i) r *= (double)i;
    return r;
}

__device__ double cg_coef(int j1, int m1, int j2, int m2, int j, int m) {
    if (m1 + m2 != m) return 0.0;
    double pref = sqrt((2.0 * j + 1.0) * dfact(j + j1 - j2) * dfact(j - j1 + j2)
                       * dfact(j1 + j2 - j) / dfact(j1 + j2 + j + 1));
    pref *= sqrt(dfact(j + m) * dfact(j - m) * dfact(j1 - m1) * dfact(j1 + m1)
               * dfact(j2 - m2) * dfact(j2 + m2));
    double s = 0.0;
    for (int k = 0; k <= j1 + j2 - j; ++k) {
        if (j1 - m1 - k < 0 || j2 + m2 - k < 0 ||
            j - j2 + m1 + k < 0 || j - j1 - m2 + k < 0) continue;
        double term = 1.0 / (dfact(k) * dfact(j1 + j2 - j - k) * dfact(j1 - m1 - k)
                           * dfact(j2 + m2 - k) * dfact(j - j2 + m1 + k)
                           * dfact(j - j1 - m2 + k));
        s += (k & 1) ? -term : term;
    }
    return pref * s;
}

__global__ void k_init() {
    int t = blockIdx.x;                        // 42 blocks, 256 threads
    g_sumsq[t * 256 + threadIdx.x] = 0.0f;     // 42*256 == 10752 exactly
    int l = c_tL[t], l1 = c_tL1[t], l2 = c_tL2[t];
    int s = l1 + l2 - l;
    for (int e = threadIdx.x; e < 81; e += blockDim.x) {
        int M = e / 9, M1 = e % 9;
        float v = 0.0f;
        if (M <= 2 * l && M1 <= 2 * l1) {
            int M2 = M + s - M1;
            if (M2 >= 0 && M2 <= 2 * l2)
                v = (float)cg_coef(l1, M1 - l1, l2, M2 - l2, l, M - l);
        }
        g_cg[t * 81 + e] = v;
    }
}

// -------------------- CG tensor product + sumsq -----------------------------
// grid: 42 triples * 16 b-chunks; block 256 = (16 j-groups) x (16 b-lanes)
__global__ void __launch_bounds__(256) k_cg(const float* __restrict__ Fs) {
    int t  = blockIdx.x >> 4;
    int b0 = (blockIdx.x & 15) << 4;
    int l  = c_tL[t], l1 = c_tL1[t], l2 = c_tL2[t];
    int d  = 2 * l + 1, d1 = 2 * l1 + 1, d2 = 2 * l2 + 1;
    int s  = l1 + l2 - l;

    __shared__ float sA[2][16][9][16];   // [ri][ch][m][b]
    __shared__ float sB[2][16][9][16];
    __shared__ float sC[81];

    for (int e = threadIdx.x; e < 81; e += 256) sC[e] = g_cg[t * 81 + e];

    int off1 = c_inoff[l1], off2 = c_inoff[l2];
    int nA = 32 * d1;   // floats per b for the A operand
    for (int e = threadIdx.x; e < 16 * nA; e += 256) {
        int bb = e / nA; int r = e - bb * nA;
        int ri = r & 1;  int cm = r >> 1;
        int ch = cm / d1; int mm = cm - ch * d1;
        sA[ri][ch][mm][bb] = Fs[(b0 + bb) * 800 + (off1 + ch * d1 + mm) * 2 + ri];
    }
    int nB = 32 * d2;
    for (int e = threadIdx.x; e < 16 * nB; e += 256) {
        int bb = e / nB; int r = e - bb * nB;
        int ri = r & 1;  int cm = r >> 1;
        int ch = cm / d2; int mm = cm - ch * d2;
        sB[ri][ch][mm][bb] = Fs[(b0 + bb) * 800 + (off2 + ch * d2 + mm) * 2 + ri];
    }
    __syncthreads();

    int lane = threadIdx.x & 15;   // b within chunk
    int j    = threadIdx.x >> 4;   // second channel index
    int Nl   = c_N[l];
    int rank = c_tRank[t];
    int l1t2 = 2 * l1, l2t2 = 2 * l2;

    for (int i = 0; i < 16; ++i) {
        int chan = rank * 256 + i * 16 + j;
        int xb   = c_xbase[l] + chan * Nl + b0 + lane;
        float ssij = 0.0f;
        for (int M = 0; M < d; ++M) {
            float fr = 0.0f, fi = 0.0f;
            int lo = M + s - l2t2; if (lo < 0) lo = 0;
            int hi = M + s;        if (hi > l1t2) hi = l1t2;
            for (int M1 = lo; M1 <= hi; ++M1) {
                float cg = sC[M * 9 + M1];
                float ar = sA[0][i][M1][lane], ai = sA[1][i][M1][lane];
                int   M2 = M + s - M1;
                float br = sB[0][j][M2][lane], bi = sB[1][j][M2][lane];
                fr += cg * (ar * br - ai * bi);
                fi += cg * (ar * bi + ai * br);
            }
            g_Xr[xb + M * 256] = fr;
            g_Xi[xb + M * 256] = fi;
            ssij += fr * fr + fi * fi;
        }
        #pragma unroll
        for (int off = 8; off; off >>= 1)
            ssij += __shfl_xor_sync(0xffffffffu, ssij, off);
        if (lane == 0) atomicAdd(&g_sumsq[c_chanbase[l] + chan], ssij);
    }
}

// ---------------- fold BN scale into weights --------------------------------
__global__ void k_prepw(const float* __restrict__ W) {
    int gid = blockIdx.x * 256 + threadIdx.x;   // 672*256 == 172032 exactly
    int cgl = gid >> 4;
    int o   = gid & 15;
    int l = 0;
    while (l < 4 && cgl >= c_chanbase[l + 1]) ++l;
    int cl = cgl - c_chanbase[l];
    float var   = g_sumsq[cgl] * (1.0f / (256.0f * (float)(2 * l + 1)));
    float scale = 1.0f / (sqrtf(var) + 1e-5f);
    int widx = (c_woff[l] + o * c_TFF[l] + cl) * 2;
    g_W2[cgl * 32 + o * 2 + 0] = W[widx + 0] * scale;
    g_W2[cgl * 32 + o * 2 + 1] = W[widx + 1] * scale;
}

// -------------------- complex GEMM: out = W' x X ----------------------------
// block: 128 threads, each owning one n; 16 outputs x complex in registers.
// grid decodes (l, n-tile, k-slice); 16 K-slices -> deterministic partials.
__global__ void __launch_bounds__(128) k_gemm() {
    int bid = blockIdx.x;
    int l = 0;
    while (l < 4 && bid >= c_gemmPrefix[l + 1]) ++l;
    int rel    = bid - c_gemmPrefix[l];
    int Nl     = c_N[l];
    int ntiles = Nl >> 7;
    int ntile  = rel % ntiles;
    int ks     = rel / ntiles;
    int slice  = c_TFF[l] >> 4;            // 80,128,160,160,144 (all /16)
    int c0     = ks * slice;
    int n      = (ntile << 7) + threadIdx.x;

    const float* Xr = g_Xr + c_xbase[l];
    const float* Xi = g_Xi + c_xbase[l];
    const float* W2 = g_W2 + (c_chanbase[l] + c0) * 32;

    float accr[16], acci[16];
    #pragma unroll
    for (int o = 0; o < 16; ++o) { accr[o] = 0.0f; acci[o] = 0.0f; }

    __shared__ float ws[16][32];
    for (int ct = 0; ct < slice; ct += 16) {
        __syncthreads();
        #pragma unroll
        for (int e = threadIdx.x; e < 512; e += 128)
            ws[e >> 5][e & 31] = W2[ct * 32 + e];
        __syncthreads();
        const float* xr = Xr + (c0 + ct) * Nl + n;
        const float* xi = Xi + (c0 + ct) * Nl + n;
        #pragma unroll
        for (int cc = 0; cc < 16; ++cc) {
            float vr = xr[cc * Nl], vi = xi[cc * Nl];
            #pragma unroll
            for (int o = 0; o < 16; ++o) {
                float wr = ws[cc][2 * o], wi = ws[cc][2 * o + 1];
                accr[o] += wr * vr - wi * vi;
                acci[o] += wr * vi + wi * vr;
            }
        }
    }
    float* P = g_partial + ks * 204800 + c_pobase[l];
    #pragma unroll
    for (int o = 0; o < 16; ++o) {
        P[(o * 2 + 0) * Nl + n] = accr[o];
        P[(o * 2 + 1) * Nl + n] = acci[o];
    }
}

// -------------------- reduce K-slices into harness layout -------------------
__global__ void k_reduce(float* __restrict__ out) {
    int p = blockIdx.x * 256 + threadIdx.x;   // 800*256 == 204800 exactly
    float ssum = 0.0f;
    #pragma unroll
    for (int ks = 0; ks < 16; ++ks) ssum += g_partial[ks * 204800 + p];
    int l = 0;
    while (l < 4 && p >= c_pobase[l + 1]) ++l;
    int rem = p - c_pobase[l];
    int Nl  = c_N[l];
    int oi  = rem / Nl;
    int n   = rem - oi * Nl;
    int o   = oi >> 1, ri = oi & 1;
    int M   = n >> 8,  b  = n & 255;
    out[b * 800 + (c_inoff[l] + o * (2 * l + 1) + M) * 2 + ri] = ssum;
}

// ---------------------------------------------------------------------------
extern "C" void kernel_launch(void* const* d_in, const int* in_sizes, int n_in,
                              void* d_out, int out_size) {
    const float* Fs = (const float*)d_in[0];
    const float* W  = (const float*)d_in[1];
    if (n_in >= 2 && in_sizes[0] == 344064) {   // defensive: metadata order
        W  = (const float*)d_in[0];
        Fs = (const float*)d_in[1];
    }
    float* out = (float*)d_out;

    k_init  <<<42,  256>>>();
    k_cg    <<<672, 256>>>(Fs);
    k_prepw <<<672, 256>>>(W);
    k_gemm  <<<800, 128>>>();
    k_reduce<<<800, 256>>>(out);
}

// round 2
// speedup vs baseline: 1.1120x; 1.1120x over previous
#include <cuda_runtime.h>
#include <math.h>

// ---------------------------------------------------------------------------
// CG tensor-product network (LMAX=4, taus=16, t_O=16), B=256.
// Pipeline: k_init (CG coefs + zero stats) -> k_cg (templated fragment
// products, register-resident operands) -> k_prepw (fold BN into W) ->
// k_gemm (register-tiled complex GEMM, 16 K-slices) -> k_reduce.
// ---------------------------------------------------------------------------

#define NT 42

__constant__ int c_tL[NT]  = {0,0,0,0,0, 1,1,1,1,1,1,1,1, 2,2,2,2,2,2,2,2,2,2,
                              3,3,3,3,3,3,3,3,3,3, 4,4,4,4,4,4,4,4,4};
__constant__ int c_tL1[NT] = {0,1,2,3,4, 1,1,2,2,3,3,4,4, 1,2,2,2,3,3,3,4,4,4,
                              2,2,3,3,3,3,4,4,4,4, 2,3,3,3,4,4,4,4,4};
__constant__ int c_tL2[NT] = {0,1,2,3,4, 0,1,1,2,2,3,3,4, 1,0,1,2,1,2,3,2,3,4,
                              1,2,0,1,2,3,1,2,3,4, 2,1,2,3,0,1,2,3,4};

__constant__ int c_chanbase[6]   = {0,1280,3328,5888,8448,10752};
__constant__ int c_N[5]          = {256,768,1280,1792,2304};
__constant__ int c_inoff[5]      = {0,16,64,144,256};
__constant__ int c_TFF[5]        = {1280,2048,2560,2560,2304};
__constant__ int c_woff[5]       = {0,20480,53248,94208,135168};
__constant__ int c_pobase[6]     = {0,8192,32768,73728,131072,204800};
__constant__ int c_gemmPrefix[6] = {0,32,128,288,512,800};
__constant__ int c_xbase[5]      = {0,327680,1900544,5177344,9764864};

// scratch (static __device__ globals: sanctioned no-alloc scratch path)
__device__ float g_cg[NT * 81];
__device__ float g_sumsq[10752];
__device__ float g_Xr[15073280];
__device__ float g_Xi[15073280];
__device__ float g_W2[344064];          // [chan][o][ri]
__device__ float g_partial[3276800];    // 16 K-slices x 204800

// -------------------------- CG coefficients --------------------------------
__device__ double dfact(int n) {
    double r = 1.0;
    for (int i = 2; i <= n; ++i) r *= (double)i;
    return r;
}

__device__ double cg_coef(int j1, int m1, int j2, int m2, int j, int m) {
    if (m1 + m2 != m) return 0.0;
    double pref = sqrt((2.0 * j + 1.0) * dfact(j + j1 - j2) * dfact(j - j1 + j2)
                       * dfact(j1 + j2 - j) / dfact(j1 + j2 + j + 1));
    pref *= sqrt(dfact(j + m) * dfact(j - m) * dfact(j1 - m1) * dfact(j1 + m1)
               * dfact(j2 - m2) * dfact(j2 + m2));
    double s = 0.0;
    for (int k = 0; k <= j1 + j2 - j; ++k) {
        if (j1 - m1 - k < 0 || j2 + m2 - k < 0 ||
            j - j2 + m1 + k < 0 || j - j1 - m2 + k < 0) continue;
        double term = 1.0 / (dfact(k) * dfact(j1 + j2 - j - k) * dfact(j1 - m1 - k)
                           * dfact(j2 + m2 - k) * dfact(j - j2 + m1 + k)
                           * dfact(j - j1 - m2 + k));
        s += (k & 1) ? -term : term;
    }
    return pref * s;
}

__global__ void k_init() {
    int t = blockIdx.x;                        // 42 blocks, 256 threads
    g_sumsq[t * 256 + threadIdx.x] = 0.0f;     // 42*256 == 10752 exactly
    int l = c_tL[t], l1 = c_tL1[t], l2 = c_tL2[t];
    int s = l1 + l2 - l;
    for (int e = threadIdx.x; e < 81; e += blockDim.x) {
        int M = e / 9, M1 = e % 9;
        float v = 0.0f;
        if (M <= 2 * l && M1 <= 2 * l1) {
            int M2 = M + s - M1;
            if (M2 >= 0 && M2 <= 2 * l2)
                v = (float)cg_coef(l1, M1 - l1, l2, M2 - l2, l, M - l);
        }
        g_cg[t * 81 + e] = v;
    }
}

// -------------------- CG tensor product (templated math) --------------------
// shared layout helpers (flat [2][16][9][16])
__device__ __forceinline__ int sidx(int ri, int ch, int m, int lane) {
    return ((ri * 16 + ch) * 9 + m) * 16 + lane;
}

template <int L, int L1, int L2, int RANK>
__device__ __forceinline__ void cg_math(const float* __restrict__ sA,
                                        const float* __restrict__ sB,
                                        const float* __restrict__ sC,
                                        int b0) {
    constexpr int D  = 2 * L + 1;
    constexpr int D1 = 2 * L1 + 1;
    constexpr int D2 = 2 * L2 + 1;
    constexpr int S  = L1 + L2 - L;
    constexpr int XB[5] = {0, 327680, 1900544, 5177344, 9764864};
    constexpr int CB[5] = {0, 1280, 3328, 5888, 8448};
    constexpr int NL = 256 * D;

    const int lane = threadIdx.x & 15;   // b within chunk
    const int j    = threadIdx.x >> 4;   // second channel index

    float br[D2], bi[D2];
    #pragma unroll
    for (int m = 0; m < D2; ++m) {
        br[m] = sB[sidx(0, j, m, lane)];
        bi[m] = sB[sidx(1, j, m, lane)];
    }

    for (int i = 0; i < 16; ++i) {
        float ar[D1], ai[D1];
        #pragma unroll
        for (int m = 0; m < D1; ++m) {
            ar[m] = sA[sidx(0, i, m, lane)];
            ai[m] = sA[sidx(1, i, m, lane)];
        }
        int chan = RANK * 256 + i * 16 + j;
        int xb   = XB[L] + chan * NL + b0 + lane;
        float ss = 0.0f;
        #pragma unroll
        for (int M = 0; M < D; ++M) {
            float fr = 0.0f, fi = 0.0f;
            #pragma unroll
            for (int M1 = 0; M1 < D1; ++M1) {
                constexpr int dummy = 0; (void)dummy;
                int M2 = M + S - M1;
                if (M2 >= 0 && M2 <= 2 * L2) {
                    float cg = sC[M * 9 + M1];
                    fr += cg * (ar[M1] * br[M2] - ai[M1] * bi[M2]);
                    fi += cg * (ar[M1] * bi[M2] + ai[M1] * br[M2]);
                }
            }
            g_Xr[xb + M * 256] = fr;
            g_Xi[xb + M * 256] = fi;
            ss += fr * fr + fi * fi;
        }
        #pragma unroll
        for (int off = 8; off; off >>= 1)
            ss += __shfl_xor_sync(0xffffffffu, ss, off);
        if (lane == 0) atomicAdd(&g_sumsq[CB[L] + chan], ss);
    }
}

// grid: 42 triples * 16 b-chunks; block 256 = (16 j) x (16 b)
__global__ void __launch_bounds__(256) k_cg(const float* __restrict__ Fs) {
    int t  = blockIdx.x >> 4;
    int b0 = (blockIdx.x & 15) << 4;
    int l1 = c_tL1[t], l2 = c_tL2[t];
    int d1 = 2 * l1 + 1, d2 = 2 * l2 + 1;

    __shared__ float sA[2 * 16 * 9 * 16];
    __shared__ float sB[2 * 16 * 9 * 16];
    __shared__ float sC[81];

    for (int e = threadIdx.x; e < 81; e += 256) sC[e] = g_cg[t * 81 + e];

    int off1 = c_inoff[l1], off2 = c_inoff[l2];
    int nA = 32 * d1;
    for (int e = threadIdx.x; e < 16 * nA; e += 256) {
        int bb = e / nA; int r = e - bb * nA;
        int ri = r & 1;  int cm = r >> 1;
        int ch = cm / d1; int mm = cm - ch * d1;
        sA[sidx(ri, ch, mm, bb)] = Fs[(b0 + bb) * 800 + (off1 + ch * d1 + mm) * 2 + ri];
    }
    int nB = 32 * d2;
    for (int e = threadIdx.x; e < 16 * nB; e += 256) {
        int bb = e / nB; int r = e - bb * nB;
        int ri = r & 1;  int cm = r >> 1;
        int ch = cm / d2; int mm = cm - ch * d2;
        sB[sidx(ri, ch, mm, bb)] = Fs[(b0 + bb) * 800 + (off2 + ch * d2 + mm) * 2 + ri];
    }
    __syncthreads();

    switch (t) {
        case  0: cg_math<0,0,0,0>(sA,sB,sC,b0); break;
        case  1: cg_math<0,1,1,1>(sA,sB,sC,b0); break;
        case  2: cg_math<0,2,2,2>(sA,sB,sC,b0); break;
        case  3: cg_math<0,3,3,3>(sA,sB,sC,b0); break;
        case  4: cg_math<0,4,4,4>(sA,sB,sC,b0); break;
        case  5: cg_math<1,1,0,0>(sA,sB,sC,b0); break;
        case  6: cg_math<1,1,1,1>(sA,sB,sC,b0); break;
        case  7: cg_math<1,2,1,2>(sA,sB,sC,b0); break;
        case  8: cg_math<1,2,2,3>(sA,sB,sC,b0); break;
        case  9: cg_math<1,3,2,4>(sA,sB,sC,b0); break;
        case 10: cg_math<1,3,3,5>(sA,sB,sC,b0); break;
        case 11: cg_math<1,4,3,6>(sA,sB,sC,b0); break;
        case 12: cg_math<1,4,4,7>(sA,sB,sC,b0); break;
        case 13: cg_math<2,1,1,0>(sA,sB,sC,b0); break;
        case 14: cg_math<2,2,0,1>(sA,sB,sC,b0); break;
        case 15: cg_math<2,2,1,2>(sA,sB,sC,b0); break;
        case 16: cg_math<2,2,2,3>(sA,sB,sC,b0); break;
        case 17: cg_math<2,3,1,4>(sA,sB,sC,b0); break;
        case 18: cg_math<2,3,2,5>(sA,sB,sC,b0); break;
        case 19: cg_math<2,3,3,6>(sA,sB,sC,b0); break;
        case 20: cg_math<2,4,2,7>(sA,sB,sC,b0); break;
        case 21: cg_math<2,4,3,8>(sA,sB,sC,b0); break;
        case 22: cg_math<2,4,4,9>(sA,sB,sC,b0); break;
        case 23: cg_math<3,2,1,0>(sA,sB,sC,b0); break;
        case 24: cg_math<3,2,2,1>(sA,sB,sC,b0); break;
        case 25: cg_math<3,3,0,2>(sA,sB,sC,b0); break;
        case 26: cg_math<3,3,1,3>(sA,sB,sC,b0); break;
        case 27: cg_math<3,3,2,4>(sA,sB,sC,b0); break;
        case 28: cg_math<3,3,3,5>(sA,sB,sC,b0); break;
        case 29: cg_math<3,4,1,6>(sA,sB,sC,b0); break;
        case 30: cg_math<3,4,2,7>(sA,sB,sC,b0); break;
        case 31: cg_math<3,4,3,8>(sA,sB,sC,b0); break;
        case 32: cg_math<3,4,4,9>(sA,sB,sC,b0); break;
        case 33: cg_math<4,2,2,0>(sA,sB,sC,b0); break;
        case 34: cg_math<4,3,1,1>(sA,sB,sC,b0); break;
        case 35: cg_math<4,3,2,2>(sA,sB,sC,b0); break;
        case 36: cg_math<4,3,3,3>(sA,sB,sC,b0); break;
        case 37: cg_math<4,4,0,4>(sA,sB,sC,b0); break;
        case 38: cg_math<4,4,1,5>(sA,sB,sC,b0); break;
        case 39: cg_math<4,4,2,6>(sA,sB,sC,b0); break;
        case 40: cg_math<4,4,3,7>(sA,sB,sC,b0); break;
        case 41: cg_math<4,4,4,8>(sA,sB,sC,b0); break;
    }
}

// ---------------- fold BN scale into weights --------------------------------
__global__ void k_prepw(const float* __restrict__ W) {
    int gid = blockIdx.x * 256 + threadIdx.x;   // 672*256 == 172032 exactly
    int cgl = gid >> 4;
    int o   = gid & 15;
    int l = 0;
    while (l < 4 && cgl >= c_chanbase[l + 1]) ++l;
    int cl = cgl - c_chanbase[l];
    float var   = g_sumsq[cgl] * (1.0f / (256.0f * (float)(2 * l + 1)));
    float scale = 1.0f / (sqrtf(var) + 1e-5f);
    int widx = (c_woff[l] + o * c_TFF[l] + cl) * 2;
    g_W2[cgl * 32 + o * 2 + 0] = W[widx + 0] * scale;
    g_W2[cgl * 32 + o * 2 + 1] = W[widx + 1] * scale;
}

// -------------------- complex GEMM: out = W' x X ----------------------------
// block: 128 threads = 4 output-quads (per warp) x 32 n-quads.
// Each thread: 4 outputs x 4 consecutive n, float4 X loads, broadcast W LDS.
__global__ void __launch_bounds__(128) k_gemm() {
    int bid = blockIdx.x;
    int l = 0;
    while (l < 4 && bid >= c_gemmPrefix[l + 1]) ++l;
    int rel    = bid - c_gemmPrefix[l];
    int Nl     = c_N[l];
    int ntiles = Nl >> 7;
    int ntile  = rel % ntiles;
    int ks     = rel / ntiles;
    int slice  = c_TFF[l] >> 4;            // 80,128,160,160,144
    int c0     = ks * slice;

    int og4 = (threadIdx.x >> 5) * 4;            // output base (warp-uniform)
    int n0  = (ntile << 7) + (threadIdx.x & 31) * 4;

    const float* __restrict__ Xr = g_Xr + c_xbase[l];
    const float* __restrict__ Xi = g_Xi + c_xbase[l];
    const float* __restrict__ W2 = g_W2 + (c_chanbase[l] + c0) * 32;

    float4 accr[4], acci[4];
    #pragma unroll
    for (int o = 0; o < 4; ++o) {
        accr[o] = make_float4(0.f, 0.f, 0.f, 0.f);
        acci[o] = make_float4(0.f, 0.f, 0.f, 0.f);
    }

    __shared__ float ws[16][32];
    for (int ct = 0; ct < slice; ct += 16) {
        __syncthreads();
        #pragma unroll
        for (int e = threadIdx.x; e < 512; e += 128)
            ws[e >> 5][e & 31] = W2[ct * 32 + e];
        __syncthreads();
        const float* xr = Xr + (c0 + ct) * Nl + n0;
        const float* xi = Xi + (c0 + ct) * Nl + n0;
        #pragma unroll
        for (int cc = 0; cc < 16; ++cc) {
            float4 vr = *(const float4*)(xr + cc * Nl);
            float4 vi = *(const float4*)(xi + cc * Nl);
            #pragma unroll
            for (int oo = 0; oo < 4; ++oo) {
                float wr = ws[cc][2 * (og4 + oo)];
                float wi = ws[cc][2 * (og4 + oo) + 1];
                accr[oo].x += wr * vr.x - wi * vi.x;
                accr[oo].y += wr * vr.y - wi * vi.y;
                accr[oo].z += wr * vr.z - wi * vi.z;
                accr[oo].w += wr * vr.w - wi * vi.w;
                acci[oo].x += wr * vi.x + wi * vr.x;
                acci[oo].y += wr * vi.y + wi * vr.y;
                acci[oo].z += wr * vi.z + wi * vr.z;
                acci[oo].w += wr * vi.w + wi * vr.w;
            }
        }
    }
    float* P = g_partial + ks * 204800 + c_pobase[l];
    #pragma unroll
    for (int oo = 0; oo < 4; ++oo) {
        int o = og4 + oo;
        *(float4*)(P + (o * 2 + 0) * Nl + n0) = accr[oo];
        *(float4*)(P + (o * 2 + 1) * Nl + n0) = acci[oo];
    }
}

// -------------------- reduce K-slices into harness layout -------------------
__global__ void k_reduce(float* __restrict__ out) {
    int p = blockIdx.x * 256 + threadIdx.x;   // 800*256 == 204800 exactly
    float ssum = 0.0f;
    #pragma unroll
    for (int ks = 0; ks < 16; ++ks) ssum += g_partial[ks * 204800 + p];
    int l = 0;
    while (l < 4 && p >= c_pobase[l + 1]) ++l;
    int rem = p - c_pobase[l];
    int Nl  = c_N[l];
    int oi  = rem / Nl;
    int n   = rem - oi * Nl;
    int o   = oi >> 1, ri = oi & 1;
    int M   = n >> 8,  b  = n & 255;
    out[b * 800 + (c_inoff[l] + o * (2 * l + 1) + M) * 2 + ri] = ssum;
}

// ---------------------------------------------------------------------------
extern "C" void kernel_launch(void* const* d_in, const int* in_sizes, int n_in,
                              void* d_out, int out_size) {
    const float* Fs = (const float*)d_in[0];
    const float* W  = (const float*)d_in[1];
    if (n_in >= 2 && in_sizes[0] == 344064) {   // defensive: metadata order
        W  = (const float*)d_in[0];
        Fs = (const float*)d_in[1];
    }
    float* out = (float*)d_out;

    k_init  <<<42,  256>>>();
    k_cg    <<<672, 256>>>(Fs);
    k_prepw <<<672, 256>>>(W);
    k_gemm  <<<800, 128>>>();
    k_reduce<<<800, 256>>>(out);
}

// round 3
// speedup vs baseline: 1.1743x; 1.0561x over previous
#include <cuda_runtime.h>
#include <math.h>

// ---------------------------------------------------------------------------
// CG tensor-product network (LMAX=4, taus=16, t_O=16), B=256.
// Pipeline: k_init (CG coefs + zero stats) -> k_cg (templated fragment
// products, register-resident operands) -> k_prepw (fold BN into W) ->
// k_gemm (barrier-free register-tiled complex GEMM, 32 K-slices) -> k_reduce.
// ---------------------------------------------------------------------------

#define NT 42

__constant__ int c_tL[NT]  = {0,0,0,0,0, 1,1,1,1,1,1,1,1, 2,2,2,2,2,2,2,2,2,2,
                              3,3,3,3,3,3,3,3,3,3, 4,4,4,4,4,4,4,4,4};
__constant__ int c_tL1[NT] = {0,1,2,3,4, 1,1,2,2,3,3,4,4, 1,2,2,2,3,3,3,4,4,4,
                              2,2,3,3,3,3,4,4,4,4, 2,3,3,3,4,4,4,4,4};
__constant__ int c_tL2[NT] = {0,1,2,3,4, 0,1,1,2,2,3,3,4, 1,0,1,2,1,2,3,2,3,4,
                              1,2,0,1,2,3,1,2,3,4, 2,1,2,3,0,1,2,3,4};

__constant__ int c_chanbase[6]   = {0,1280,3328,5888,8448,10752};
__constant__ int c_N[5]          = {256,768,1280,1792,2304};
__constant__ int c_inoff[5]      = {0,16,64,144,256};
__constant__ int c_TFF[5]        = {1280,2048,2560,2560,2304};
__constant__ int c_woff[5]       = {0,20480,53248,94208,135168};
__constant__ int c_pobase[6]     = {0,8192,32768,73728,131072,204800};
__constant__ int c_gemmPrefix[6] = {0,64,256,576,1024,1600};
__constant__ int c_xbase[5]      = {0,327680,1900544,5177344,9764864};

// scratch (static __device__ globals: sanctioned no-alloc scratch path)
__device__ float g_cg[NT * 81];
__device__ float g_sumsq[10752];
__device__ float g_Xr[15073280];
__device__ float g_Xi[15073280];
__device__ float g_W2[344064];          // [chan][o][ri]
__device__ float g_partial[6553600];    // 32 K-slices x 204800

// -------------------------- CG coefficients --------------------------------
__device__ double dfact(int n) {
    double r = 1.0;
    for (int i = 2; i <= n; ++i) r *= (double)i;
    return r;
}

__device__ double cg_coef(int j1, int m1, int j2, int m2, int j, int m) {
    if (m1 + m2 != m) return 0.0;
    double pref = sqrt((2.0 * j + 1.0) * dfact(j + j1 - j2) * dfact(j - j1 + j2)
                       * dfact(j1 + j2 - j) / dfact(j1 + j2 + j + 1));
    pref *= sqrt(dfact(j + m) * dfact(j - m) * dfact(j1 - m1) * dfact(j1 + m1)
               * dfact(j2 - m2) * dfact(j2 + m2));
    double s = 0.0;
    for (int k = 0; k <= j1 + j2 - j; ++k) {
        if (j1 - m1 - k < 0 || j2 + m2 - k < 0 ||
            j - j2 + m1 + k < 0 || j - j1 - m2 + k < 0) continue;
        double term = 1.0 / (dfact(k) * dfact(j1 + j2 - j - k) * dfact(j1 - m1 - k)
                           * dfact(j2 + m2 - k) * dfact(j - j2 + m1 + k)
                           * dfact(j - j1 - m2 + k));
        s += (k & 1) ? -term : term;
    }
    return pref * s;
}

__global__ void k_init() {
    int t = blockIdx.x;                        // 42 blocks, 256 threads
    g_sumsq[t * 256 + threadIdx.x] = 0.0f;     // 42*256 == 10752 exactly
    int l = c_tL[t], l1 = c_tL1[t], l2 = c_tL2[t];
    int s = l1 + l2 - l;
    for (int e = threadIdx.x; e < 81; e += blockDim.x) {
        int M = e / 9, M1 = e % 9;
        float v = 0.0f;
        if (M <= 2 * l && M1 <= 2 * l1) {
            int M2 = M + s - M1;
            if (M2 >= 0 && M2 <= 2 * l2)
                v = (float)cg_coef(l1, M1 - l1, l2, M2 - l2, l, M - l);
        }
        g_cg[t * 81 + e] = v;
    }
}

// -------------------- CG tensor product (templated math) --------------------
// shared layout helpers (flat [2][16][9][16])
__device__ __forceinline__ int sidx(int ri, int ch, int m, int lane) {
    return ((ri * 16 + ch) * 9 + m) * 16 + lane;
}

template <int L, int L1, int L2, int RANK>
__device__ __forceinline__ void cg_math(const float* __restrict__ sA,
                                        const float* __restrict__ sB,
                                        const float* __restrict__ sC,
                                        int b0) {
    constexpr int D  = 2 * L + 1;
    constexpr int D1 = 2 * L1 + 1;
    constexpr int D2 = 2 * L2 + 1;
    constexpr int S  = L1 + L2 - L;
    constexpr int XB[5] = {0, 327680, 1900544, 5177344, 9764864};
    constexpr int CB[5] = {0, 1280, 3328, 5888, 8448};
    constexpr int NL = 256 * D;

    const int lane = threadIdx.x & 15;   // b within chunk
    const int j    = threadIdx.x >> 4;   // second channel index

    float br[D2], bi[D2];
    #pragma unroll
    for (int m = 0; m < D2; ++m) {
        br[m] = sB[sidx(0, j, m, lane)];
        bi[m] = sB[sidx(1, j, m, lane)];
    }

    for (int i = 0; i < 16; ++i) {
        float ar[D1], ai[D1];
        #pragma unroll
        for (int m = 0; m < D1; ++m) {
            ar[m] = sA[sidx(0, i, m, lane)];
            ai[m] = sA[sidx(1, i, m, lane)];
        }
        int chan = RANK * 256 + i * 16 + j;
        int xb   = XB[L] + chan * NL + b0 + lane;
        float ss = 0.0f;
        #pragma unroll
        for (int M = 0; M < D; ++M) {
            float fr = 0.0f, fi = 0.0f;
            #pragma unroll
            for (int M1 = 0; M1 < D1; ++M1) {
                int M2 = M + S - M1;
                if (M2 >= 0 && M2 <= 2 * L2) {
                    float cg = sC[M * 9 + M1];
                    fr += cg * (ar[M1] * br[M2] - ai[M1] * bi[M2]);
                    fi += cg * (ar[M1] * bi[M2] + ai[M1] * br[M2]);
                }
            }
            g_Xr[xb + M * 256] = fr;
            g_Xi[xb + M * 256] = fi;
            ss += fr * fr + fi * fi;
        }
        #pragma unroll
        for (int off = 8; off; off >>= 1)
            ss += __shfl_xor_sync(0xffffffffu, ss, off);
        if (lane == 0) atomicAdd(&g_sumsq[CB[L] + chan], ss);
    }
}

// grid: 42 triples * 16 b-chunks; block 256 = (16 j) x (16 b)
__global__ void __launch_bounds__(256) k_cg(const float* __restrict__ Fs) {
    int t  = blockIdx.x >> 4;
    int b0 = (blockIdx.x & 15) << 4;
    int l1 = c_tL1[t], l2 = c_tL2[t];
    int d1 = 2 * l1 + 1, d2 = 2 * l2 + 1;

    __shared__ float sA[2 * 16 * 9 * 16];
    __shared__ float sB[2 * 16 * 9 * 16];
    __shared__ float sC[81];

    for (int e = threadIdx.x; e < 81; e += 256) sC[e] = g_cg[t * 81 + e];

    int off1 = c_inoff[l1], off2 = c_inoff[l2];
    int nA = 32 * d1;
    for (int e = threadIdx.x; e < 16 * nA; e += 256) {
        int bb = e / nA; int r = e - bb * nA;
        int ri = r & 1;  int cm = r >> 1;
        int ch = cm / d1; int mm = cm - ch * d1;
        sA[sidx(ri, ch, mm, bb)] = Fs[(b0 + bb) * 800 + (off1 + ch * d1 + mm) * 2 + ri];
    }
    int nB = 32 * d2;
    for (int e = threadIdx.x; e < 16 * nB; e += 256) {
        int bb = e / nB; int r = e - bb * nB;
        int ri = r & 1;  int cm = r >> 1;
        int ch = cm / d2; int mm = cm - ch * d2;
        sB[sidx(ri, ch, mm, bb)] = Fs[(b0 + bb) * 800 + (off2 + ch * d2 + mm) * 2 + ri];
    }
    __syncthreads();

    switch (t) {
        case  0: cg_math<0,0,0,0>(sA,sB,sC,b0); break;
        case  1: cg_math<0,1,1,1>(sA,sB,sC,b0); break;
        case  2: cg_math<0,2,2,2>(sA,sB,sC,b0); break;
        case  3: cg_math<0,3,3,3>(sA,sB,sC,b0); break;
        case  4: cg_math<0,4,4,4>(sA,sB,sC,b0); break;
        case  5: cg_math<1,1,0,0>(sA,sB,sC,b0); break;
        case  6: cg_math<1,1,1,1>(sA,sB,sC,b0); break;
        case  7: cg_math<1,2,1,2>(sA,sB,sC,b0); break;
        case  8: cg_math<1,2,2,3>(sA,sB,sC,b0); break;
        case  9: cg_math<1,3,2,4>(sA,sB,sC,b0); break;
        case 10: cg_math<1,3,3,5>(sA,sB,sC,b0); break;
        case 11: cg_math<1,4,3,6>(sA,sB,sC,b0); break;
        case 12: cg_math<1,4,4,7>(sA,sB,sC,b0); break;
        case 13: cg_math<2,1,1,0>(sA,sB,sC,b0); break;
        case 14: cg_math<2,2,0,1>(sA,sB,sC,b0); break;
        case 15: cg_math<2,2,1,2>(sA,sB,sC,b0); break;
        case 16: cg_math<2,2,2,3>(sA,sB,sC,b0); break;
        case 17: cg_math<2,3,1,4>(sA,sB,sC,b0); break;
        case 18: cg_math<2,3,2,5>(sA,sB,sC,b0); break;
        case 19: cg_math<2,3,3,6>(sA,sB,sC,b0); break;
        case 20: cg_math<2,4,2,7>(sA,sB,sC,b0); break;
        case 21: cg_math<2,4,3,8>(sA,sB,sC,b0); break;
        case 22: cg_math<2,4,4,9>(sA,sB,sC,b0); break;
        case 23: cg_math<3,2,1,0>(sA,sB,sC,b0); break;
        case 24: cg_math<3,2,2,1>(sA,sB,sC,b0); break;
        case 25: cg_math<3,3,0,2>(sA,sB,sC,b0); break;
        case 26: cg_math<3,3,1,3>(sA,sB,sC,b0); break;
        case 27: cg_math<3,3,2,4>(sA,sB,sC,b0); break;
        case 28: cg_math<3,3,3,5>(sA,sB,sC,b0); break;
        case 29: cg_math<3,4,1,6>(sA,sB,sC,b0); break;
        case 30: cg_math<3,4,2,7>(sA,sB,sC,b0); break;
        case 31: cg_math<3,4,3,8>(sA,sB,sC,b0); break;
        case 32: cg_math<3,4,4,9>(sA,sB,sC,b0); break;
        case 33: cg_math<4,2,2,0>(sA,sB,sC,b0); break;
        case 34: cg_math<4,3,1,1>(sA,sB,sC,b0); break;
        case 35: cg_math<4,3,2,2>(sA,sB,sC,b0); break;
        case 36: cg_math<4,3,3,3>(sA,sB,sC,b0); break;
        case 37: cg_math<4,4,0,4>(sA,sB,sC,b0); break;
        case 38: cg_math<4,4,1,5>(sA,sB,sC,b0); break;
        case 39: cg_math<4,4,2,6>(sA,sB,sC,b0); break;
        case 40: cg_math<4,4,3,7>(sA,sB,sC,b0); break;
        case 41: cg_math<4,4,4,8>(sA,sB,sC,b0); break;
    }
}

// ---------------- fold BN scale into weights --------------------------------
__global__ void k_prepw(const float* __restrict__ W) {
    int gid = blockIdx.x * 256 + threadIdx.x;   // 672*256 == 172032 exactly
    int cgl = gid >> 4;
    int o   = gid & 15;
    int l = 0;
    while (l < 4 && cgl >= c_chanbase[l + 1]) ++l;
    int cl = cgl - c_chanbase[l];
    float var   = g_sumsq[cgl] * (1.0f / (256.0f * (float)(2 * l + 1)));
    float scale = 1.0f / (sqrtf(var) + 1e-5f);
    int widx = (c_woff[l] + o * c_TFF[l] + cl) * 2;
    g_W2[cgl * 32 + o * 2 + 0] = W[widx + 0] * scale;
    g_W2[cgl * 32 + o * 2 + 1] = W[widx + 1] * scale;
}

// -------------------- complex GEMM: out = W' x X ----------------------------
// Barrier-free: weights read per-channel as warp-uniform __ldg (L1/L2 hot),
// X streamed as float4, 32 K-slices for grid parallelism (1600 blocks).
// block: 128 threads = 4 warps (each warp owns 4 outputs) x 32 n-quads.
__global__ void __launch_bounds__(128) k_gemm() {
    int bid = blockIdx.x;
    int l = 0;
    while (l < 4 && bid >= c_gemmPrefix[l + 1]) ++l;
    int rel    = bid - c_gemmPrefix[l];
    int Nl     = c_N[l];
    int ntiles = Nl >> 7;
    int ntile  = rel % ntiles;
    int ks     = rel / ntiles;
    int slice  = c_TFF[l] >> 5;            // 40,64,80,80,72 (all /4)
    int c0     = ks * slice;

    int og4 = (threadIdx.x >> 5) << 2;           // output base (warp-uniform)
    int n0  = (ntile << 7) + ((threadIdx.x & 31) << 2);

    const float* __restrict__ Xr = g_Xr + c_xbase[l] + c0 * Nl + n0;
    const float* __restrict__ Xi = g_Xi + c_xbase[l] + c0 * Nl + n0;
    const float* __restrict__ Wp = g_W2 + (c_chanbase[l] + c0) * 32 + 2 * og4;

    float4 accr[4], acci[4];
    #pragma unroll
    for (int o = 0; o < 4; ++o) {
        accr[o] = make_float4(0.f, 0.f, 0.f, 0.f);
        acci[o] = make_float4(0.f, 0.f, 0.f, 0.f);
    }

    #pragma unroll 4
    for (int cc = 0; cc < slice; ++cc) {
        float4 vr = __ldg((const float4*)(Xr + cc * Nl));
        float4 vi = __ldg((const float4*)(Xi + cc * Nl));
        const float2* wrow = (const float2*)(Wp + cc * 32);
        #pragma unroll
        for (int oo = 0; oo < 4; ++oo) {
            float2 w = __ldg(wrow + oo);
            accr[oo].x += w.x * vr.x - w.y * vi.x;
            accr[oo].y += w.x * vr.y - w.y * vi.y;
            accr[oo].z += w.x * vr.z - w.y * vi.z;
            accr[oo].w += w.x * vr.w - w.y * vi.w;
            acci[oo].x += w.x * vi.x + w.y * vr.x;
            acci[oo].y += w.x * vi.y + w.y * vr.y;
            acci[oo].z += w.x * vi.z + w.y * vr.z;
            acci[oo].w += w.x * vi.w + w.y * vr.w;
        }
    }

    float* P = g_partial + ks * 204800 + c_pobase[l];
    #pragma unroll
    for (int oo = 0; oo < 4; ++oo) {
        int o = og4 + oo;
        *(float4*)(P + (o * 2 + 0) * Nl + n0) = accr[oo];
        *(float4*)(P + (o * 2 + 1) * Nl + n0) = acci[oo];
    }
}

// -------------------- reduce K-slices into harness layout -------------------
__global__ void k_reduce(float* __restrict__ out) {
    int p = blockIdx.x * 256 + threadIdx.x;   // 800*256 == 204800 exactly
    float ssum = 0.0f;
    #pragma unroll
    for (int ks = 0; ks < 32; ++ks) ssum += g_partial[ks * 204800 + p];
    int l = 0;
    while (l < 4 && p >= c_pobase[l + 1]) ++l;
    int rem = p - c_pobase[l];
    int Nl  = c_N[l];
    int oi  = rem / Nl;
    int n   = rem - oi * Nl;
    int o   = oi >> 1, ri = oi & 1;
    int M   = n >> 8,  b  = n & 255;
    out[b * 800 + (c_inoff[l] + o * (2 * l + 1) + M) * 2 + ri] = ssum;
}

// ---------------------------------------------------------------------------
extern "C" void kernel_launch(void* const* d_in, const int* in_sizes, int n_in,
                              void* d_out, int out_size) {
    const float* Fs = (const float*)d_in[0];
    const float* W  = (const float*)d_in[1];
    if (n_in >= 2 && in_sizes[0] == 344064) {   // defensive: metadata order
        W  = (const float*)d_in[0];
        Fs = (const float*)d_in[1];
    }
    float* out = (float*)d_out;

    k_init  <<<42,  256>>>();
    k_cg    <<<672, 256>>>(Fs);
    k_prepw <<<672, 256>>>(W);
    k_gemm  <<<1600, 128>>>();
    k_reduce<<<800, 256>>>(out);
}